// round 4
// baseline (speedup 1.0000x reference)
#include <cuda_runtime.h>
#include <cstdint>

// FlattenHead: segmented row compaction (persistent grid-stride version).
// x: [B=16, T=4096, D=1024] fp32, seq_lens: [16] int32.
// out rows = concat of x[b, 0:seq_lens[b]] per batch.
//
// R4: launch exactly one wave (148 SMs x 8 CTAs); each block strides over the
// VALID 8-row chunks only. Chunk->batch mapping via smem prefix table.

static constexpr int B = 16;
static constexpr int T = 4096;
static constexpr int VEC_PER_ROW = 256;                 // D/4 float4 per row
static constexpr int ROWS_PER_BLK = 8;
static constexpr int VECS_PER_BLK = ROWS_PER_BLK * VEC_PER_ROW;  // 2048
static constexpr int GRID = 148 * 8;                    // one full wave

__global__ __launch_bounds__(256, 8)
void flatten_head_kernel(const float4* __restrict__ x,
                         const int* __restrict__ seq_lens,
                         float4* __restrict__ out)
{
    __shared__ int s_len[B], s_rowPre[B], s_chunkPre[B], s_total;

    if (threadIdx.x == 0) {
        int r = 0, c = 0;
#pragma unroll
        for (int i = 0; i < B; ++i) {
            const int l = seq_lens[i];
            s_len[i] = l;
            s_rowPre[i] = r;
            s_chunkPre[i] = c;
            r += l;
            c += (l + ROWS_PER_BLK - 1) >> 3;
        }
        s_total = c;
    }
    __syncthreads();

    const int total = s_total;
    const int tid = threadIdx.x;

    for (int g = blockIdx.x; g < total; g += GRID) {
        // Find batch: last i with chunkPre[i] <= g (zero-len batches skip
        // naturally since their chunk range is empty).
        int b = 0;
#pragma unroll
        for (int i = 1; i < B; ++i)
            b = (g >= s_chunkPre[i]) ? i : b;

        const int t0 = (g - s_chunkPre[b]) << 3;        // row within batch
        const float4* __restrict__ src = x   + ((b * T + t0) * VEC_PER_ROW);
        float4*       __restrict__ dst = out + ((s_rowPre[b] + t0) * VEC_PER_ROW);
        const int nvalid = min(s_len[b] - t0, ROWS_PER_BLK) * VEC_PER_ROW;

        if (nvalid == VECS_PER_BLK) {
            // Fast path: front-batch 8 loads (MLP=8), then 8 stores.
            float4 r[ROWS_PER_BLK];
#pragma unroll
            for (int k = 0; k < ROWS_PER_BLK; ++k)
                r[k] = src[tid + k * 256];
#pragma unroll
            for (int k = 0; k < ROWS_PER_BLK; ++k)
                dst[tid + k * 256] = r[k];
        } else {
            // Boundary chunk (at most one per batch): predicated copy.
#pragma unroll
            for (int k = 0; k < ROWS_PER_BLK; ++k) {
                const int idx = tid + k * 256;
                if (idx < nvalid) dst[idx] = src[idx];
            }
        }
    }
}

extern "C" void kernel_launch(void* const* d_in, const int* in_sizes, int n_in,
                              void* d_out, int out_size)
{
    (void)out_size;
    const float4* x;
    const int*    lens;
    if (in_sizes[0] == B) {                  // lens-first ordering (defensive)
        lens = (const int*)d_in[0];
        x    = (const float4*)((n_in > 1) ? d_in[1] : d_in[0]);
    } else {
        x    = (const float4*)d_in[0];
        lens = (const int*)((n_in > 1) ? d_in[1] : d_in[0]);
    }
    float4* out = (float4*)d_out;

    flatten_head_kernel<<<GRID, 256>>>(x, lens, out);
}

// round 5
// speedup vs baseline: 1.0468x; 1.0468x over previous
#include <cuda_runtime.h>
#include <cstdint>

// FlattenHead: segmented row compaction.
// x: [B=16, T=4096, D=1024] fp32, seq_lens: [16] int32.
// out rows = concat of x[b, 0:seq_lens[b]] per batch.
//
// R5: flat grid (R3 winner) + (a) launch_bounds(256,6) so ptxas has 42 regs
// and can keep all 8 LDG.128 in flight (true MLP=8), (b) streaming cache
// hints (evict-first) on both streams to stop L2 thrash.

static constexpr int B = 16;
static constexpr int T = 4096;
static constexpr int VEC_PER_ROW = 256;       // D/4 float4 per row
static constexpr int ROWS_PER_BLK = 8;
static constexpr int VECS_PER_BLK = ROWS_PER_BLK * VEC_PER_ROW;  // 2048
static constexpr int BLKS_PER_BATCH = T / ROWS_PER_BLK;           // 512

__device__ __forceinline__ float4 ldcs4(const float4* p) {
    float4 v;
    asm volatile("ld.global.cs.v4.f32 {%0,%1,%2,%3}, [%4];"
                 : "=f"(v.x), "=f"(v.y), "=f"(v.z), "=f"(v.w) : "l"(p));
    return v;
}
__device__ __forceinline__ void stcs4(float4* p, float4 v) {
    asm volatile("st.global.cs.v4.f32 [%0], {%1,%2,%3,%4};"
                 :: "l"(p), "f"(v.x), "f"(v.y), "f"(v.z), "f"(v.w) : "memory");
}

__global__ __launch_bounds__(256, 6)
void flatten_head_kernel(const float4* __restrict__ x,
                         const int* __restrict__ seq_lens,
                         float4* __restrict__ out)
{
    const int blk = blockIdx.x;
    const int b   = blk >> 9;                 // / BLKS_PER_BATCH
    const int t0  = (blk & (BLKS_PER_BATCH - 1)) * ROWS_PER_BLK;

    const int len = seq_lens[b];
    if (t0 >= len) return;                    // fully-invalid chunk

    // Exclusive prefix of lens[0..b-1], 32-bit (sum <= 65536).
    int prefix = 0;
#pragma unroll
    for (int i = 0; i < B; ++i)
        prefix += (i < b) ? seq_lens[i] : 0;

    const int tid = threadIdx.x;
    const float4* __restrict__ src = x   + ((b * T + t0) * VEC_PER_ROW);
    float4*       __restrict__ dst = out + ((prefix + t0) * VEC_PER_ROW);

    const int nvalid = min(len - t0, ROWS_PER_BLK) * VEC_PER_ROW;

    if (nvalid == VECS_PER_BLK) {
        // Fast path: front-batch 8 streaming loads (MLP=8), then 8 stores.
        float4 r[ROWS_PER_BLK];
#pragma unroll
        for (int k = 0; k < ROWS_PER_BLK; ++k)
            r[k] = ldcs4(src + tid + k * 256);
#pragma unroll
        for (int k = 0; k < ROWS_PER_BLK; ++k)
            stcs4(dst + tid + k * 256, r[k]);
    } else {
        // Boundary chunk (at most one per batch): predicated copy.
#pragma unroll
        for (int k = 0; k < ROWS_PER_BLK; ++k) {
            const int idx = tid + k * 256;
            if (idx < nvalid) stcs4(dst + idx, ldcs4(src + idx));
        }
    }
}

extern "C" void kernel_launch(void* const* d_in, const int* in_sizes, int n_in,
                              void* d_out, int out_size)
{
    (void)out_size;
    const float4* x;
    const int*    lens;
    if (in_sizes[0] == B) {                   // lens-first ordering (defensive)
        lens = (const int*)d_in[0];
        x    = (const float4*)((n_in > 1) ? d_in[1] : d_in[0]);
    } else {
        x    = (const float4*)d_in[0];
        lens = (const int*)((n_in > 1) ? d_in[1] : d_in[0]);
    }
    float4* out = (float4*)d_out;

    flatten_head_kernel<<<B * BLKS_PER_BATCH, 256>>>(x, lens, out);
}